// round 17
// baseline (speedup 1.0000x reference)
#include <cuda_runtime.h>
#include <math.h>
#include <stdint.h>

#define Bq   8
#define Lseq 2048
#define Dk   300
#define Hk   150
#define NROWS (Bq*Lseq)     // 16384

// scratch (allocation-free rule -> __device__ globals)
__device__ float g_Ah[(size_t)NROWS*160];          // [row][160], cols>=150 zero
__device__ float g_P [(size_t)NROWS*160];          // [row][160], cols>=150 zero
__device__ float g_Qt[(size_t)256*160*64];         // per 64-q-tile transposed [tile][h(160)][q(64)]

// ---------------- f32x2 helpers ----------------
typedef unsigned long long u64t;
__device__ __forceinline__ void ffma2(u64t &d, u64t a, u64t b) {
    asm("fma.rn.f32x2 %0, %1, %2, %0;" : "+l"(d) : "l"(a), "l"(b));
}
__device__ __forceinline__ float lo_f(u64t v){ return __uint_as_float((unsigned)v); }
__device__ __forceinline__ float hi_f(u64t v){ return __uint_as_float((unsigned)(v>>32)); }
__device__ __forceinline__ u64t pack2(float x, float y){
    u64t d; asm("mov.b64 %0, {%1,%2};" : "=l"(d)
                : "r"(__float_as_uint(x)), "r"(__float_as_uint(y))); return d;
}

// ---------------- bf16 mma helpers (plain mma.sync m16n8k16) ----------------
__device__ __forceinline__ void mma16(float* c, uint32_t a0, uint32_t a1,
                                      uint32_t a2, uint32_t a3,
                                      uint32_t b0, uint32_t b1) {
    asm volatile(
        "mma.sync.aligned.m16n8k16.row.col.f32.bf16.bf16.f32 "
        "{%0,%1,%2,%3}, {%4,%5,%6,%7}, {%8,%9}, {%0,%1,%2,%3};"
        : "+f"(c[0]), "+f"(c[1]), "+f"(c[2]), "+f"(c[3])
        : "r"(a0), "r"(a1), "r"(a2), "r"(a3), "r"(b0), "r"(b1));
}
// 2-term bf16 split of a float pair: h = bf16x2(x0,x1), l = bf16x2(residuals)
__device__ __forceinline__ void splitb2(float x0, float x1, uint32_t &h, uint32_t &l) {
    uint32_t hh;
    asm("cvt.rn.bf16x2.f32 %0, %1, %2;" : "=r"(hh) : "f"(x1), "f"(x0));
    float h0 = __uint_as_float(hh << 16);
    float h1 = __uint_as_float(hh & 0xffff0000u);
    uint32_t ll;
    asm("cvt.rn.bf16x2.f32 %0, %1, %2;" : "=r"(ll) : "f"(x1 - h1), "f"(x0 - h0));
    h = hh; l = ll;
}

// fast exp via FMA-pipe polynomial; x <= 0 expected
__device__ __forceinline__ float fexp(float x) {
    float y = fmaxf(x * 1.4426950408889634f, -126.0f);
    int   ii = __float2int_rn(y);
    float f = y - (float)ii;
    float p = 0.0013333558f;
    p = p*f + 0.009618129f;
    p = p*f + 0.055504109f;
    p = p*f + 0.24022651f;
    p = p*f + 0.69314718f;
    p = p*f + 1.0f;
    return __int_as_float((ii + 127) << 23) * p;
}

// ---------------------------------------------------------------------------
// Kernel 1: gated projection (f32x2 over n-pairs); Q blocks fuse P = Qh@Wg+bg
// and store Qh TRANSPOSED per 64-q-tile into g_Qt.  (unchanged from R16)
// ---------------------------------------------------------------------------
__global__ __launch_bounds__(256) void gate_kernel(
    const float* __restrict__ Q, const float* __restrict__ A,
    const float* __restrict__ Wi, const float* __restrict__ Wu,
    const float* __restrict__ Wg,
    const float* __restrict__ bi, const float* __restrict__ bu,
    const float* __restrict__ bg)
{
    __shared__ float sm[10560];
    float* Xs  = sm;          // [32][30]
    float* Wis = sm + 960;    // [30][160]
    float* Wus = sm + 5760;   // [30][160]
    float* Qhs = sm;          // [32][160] (P phase)
    float* Wgs = sm + 5760;   // [30][160] (P phase)

    const int tid = threadIdx.x;
    const int tx = tid & 15, ty = tid >> 4;
    const bool isQ = (blockIdx.x < 512);
    const int row0 = (blockIdx.x & 511) * 32;
    const float* X = isQ ? Q : A;

    u64t ai2[2][5], au2[2][5];
    #pragma unroll
    for (int i = 0; i < 2; i++)
        #pragma unroll
        for (int jp = 0; jp < 5; jp++) { ai2[i][jp] = 0ull; au2[i][jp] = 0ull; }

    for (int kt = 0; kt < 10; kt++) {
        for (int idx = tid; idx < 32*30; idx += 256) {
            int m = idx / 30, kk = idx - m*30;
            Xs[idx] = X[(size_t)(row0 + m) * Dk + kt*30 + kk];
        }
        for (int idx = tid; idx < 30*160; idx += 256) {
            int kk = idx / 160, n = idx - kk*160;
            float wi = 0.f, wu = 0.f;
            if (n < Hk) { int g = (kt*30 + kk) * Hk + n; wi = Wi[g]; wu = Wu[g]; }
            Wis[idx] = wi; Wus[idx] = wu;
        }
        __syncthreads();
        #pragma unroll 5
        for (int k = 0; k < 30; k++) {
            float x0 = Xs[(ty*2    )*30 + k];
            float x1 = Xs[(ty*2 + 1)*30 + k];
            u64t x0p = pack2(x0, x0), x1p = pack2(x1, x1);
            #pragma unroll
            for (int jp = 0; jp < 5; jp++) {
                u64t wi = *(const u64t*)&Wis[k*160 + 2*(tx + 16*jp)];
                u64t wu = *(const u64t*)&Wus[k*160 + 2*(tx + 16*jp)];
                ffma2(ai2[0][jp], x0p, wi); ffma2(ai2[1][jp], x1p, wi);
                ffma2(au2[0][jp], x0p, wu); ffma2(au2[1][jp], x1p, wu);
            }
        }
        __syncthreads();
    }

    // nonlinearity
    float hv[2][10];
    #pragma unroll
    for (int i = 0; i < 2; i++)
        #pragma unroll
        for (int jp = 0; jp < 5; jp++) {
            int n0 = 2*(tx + 16*jp);
            bool v = (n0 < Hk);
            float bi0 = v ? bi[n0] : 0.f, bi1 = v ? bi[n0+1] : 0.f;
            float bu0 = v ? bu[n0] : 0.f, bu1 = v ? bu[n0+1] : 0.f;
            float s0 = 1.f/(1.f + __expf(-(lo_f(ai2[i][jp]) + bi0)));
            float s1 = 1.f/(1.f + __expf(-(hi_f(ai2[i][jp]) + bi1)));
            float h0 = s0 * tanhf(lo_f(au2[i][jp]) + bu0);
            float h1 = s1 * tanhf(hi_f(au2[i][jp]) + bu1);
            hv[i][jp*2]   = v ? h0 : 0.f;
            hv[i][jp*2+1] = v ? h1 : 0.f;
        }

    if (!isQ) {
        #pragma unroll
        for (int i = 0; i < 2; i++)
            #pragma unroll
            for (int jp = 0; jp < 5; jp++) {
                int n0 = 2*(tx + 16*jp);
                *(u64t*)&g_Ah[(size_t)(row0 + ty*2 + i)*160 + n0] =
                    pack2(hv[i][jp*2], hv[i][jp*2+1]);
            }
        return;
    }

    // transposed Qh store: g_Qt[t64][h][q], plus zero rows 150..159
    {
        int t64 = row0 >> 6, qb = row0 & 63;
        size_t tb = (size_t)t64 * 160 * 64;
        #pragma unroll
        for (int i = 0; i < 2; i++)
            #pragma unroll
            for (int jp = 0; jp < 5; jp++) {
                int n0 = 2*(tx + 16*jp);
                if (n0 < Hk) {
                    g_Qt[tb + (size_t)n0*64     + qb + ty*2 + i] = hv[i][jp*2];
                    g_Qt[tb + (size_t)(n0+1)*64 + qb + ty*2 + i] = hv[i][jp*2+1];
                }
            }
        for (int idx = tid; idx < 10*32; idx += 256) {
            int h = 150 + (idx >> 5), q = qb + (idx & 31);
            g_Qt[tb + (size_t)h*64 + q] = 0.f;
        }
    }

    // P = Qh @ Wg + bg
    __syncthreads();
    #pragma unroll
    for (int i = 0; i < 2; i++)
        #pragma unroll
        for (int jp = 0; jp < 5; jp++) {
            int n0 = 2*(tx + 16*jp);
            *(u64t*)&Qhs[(ty*2 + i)*160 + n0] = pack2(hv[i][jp*2], hv[i][jp*2+1]);
        }
    __syncthreads();

    u64t ap2[2][5];
    #pragma unroll
    for (int i = 0; i < 2; i++)
        #pragma unroll
        for (int jp = 0; jp < 5; jp++) ap2[i][jp] = 0ull;

    for (int kt = 0; kt < 5; kt++) {
        for (int idx = tid; idx < 30*160; idx += 256) {
            int kk = idx / 160, n = idx - kk*160;
            Wgs[idx] = (n < Hk) ? Wg[(kt*30 + kk) * Hk + n] : 0.f;
        }
        __syncthreads();
        #pragma unroll 5
        for (int k = 0; k < 30; k++) {
            float q0 = Qhs[(ty*2    )*160 + kt*30 + k];
            float q1 = Qhs[(ty*2 + 1)*160 + kt*30 + k];
            u64t q0p = pack2(q0, q0), q1p = pack2(q1, q1);
            #pragma unroll
            for (int jp = 0; jp < 5; jp++) {
                u64t wg = *(const u64t*)&Wgs[k*160 + 2*(tx + 16*jp)];
                ffma2(ap2[0][jp], q0p, wg);
                ffma2(ap2[1][jp], q1p, wg);
            }
        }
        __syncthreads();
    }
    #pragma unroll
    for (int i = 0; i < 2; i++)
        #pragma unroll
        for (int jp = 0; jp < 5; jp++) {
            int n0 = 2*(tx + 16*jp);
            bool v = (n0 < Hk);
            float p0 = v ? lo_f(ap2[i][jp]) + bg[n0]   : 0.f;
            float p1 = v ? hi_f(ap2[i][jp]) + bg[n0+1] : 0.f;
            *(u64t*)&g_P[(size_t)(row0 + ty*2 + i)*160 + n0] = pack2(p0, p1);
        }
}

// ---------------------------------------------------------------------------
// Kernel 2: flash attention, bf16 m16n8k16 2-term split with PRE-SPLIT packed
// operands in SMEM (uint2 {hi_bf16x2, lo_bf16x2}); B-operands stored
// [k-position][n] so B-fragment LDS broadcast over tig and spread over g.
// 512 threads; warp pair (w, w+8): S split along q, O split along h.
// ---------------------------------------------------------------------------
// word-strides (in uint2 units unless noted)
#define UA 84      // AhW row stride (uint2): [r(128)][p(80)+pad]
#define UP 65      // PW  p-row stride: [p(80)][q(64)+pad]
#define UQ 161     // QtW p-row stride: [p(32)][col(160)+pad]
#define UE 130     // EW  p-row stride: [p(32)][r(128)+pad]
// float-word offsets
#define OFF_AH 0
#define OFF_PW 21504                       // 128*UA*2
#define OFF_QT (OFF_PW + 80*UP*2)          // 21504+10400 = 31904
#define OFF_EW (OFF_QT + 32*UQ*2)          // 31904+10304 = 42208
#define OFF_PM (OFF_EW + 32*UE*2)          // 42208+8320  = 50528
#define OFF_PS (OFF_PM + 256)              // 50784
#define SMF_TOT (OFF_PS + 256)             // 51040 floats = 204160 B
#define ST_H 154

__global__ __launch_bounds__(512, 1) void attn_kernel(
    const float* __restrict__ Wt, const float* __restrict__ bt,
    float* __restrict__ out)
{
    extern __shared__ __align__(16) float sm[];
    uint2* AhW = (uint2*)(sm + OFF_AH);
    uint2* PW  = (uint2*)(sm + OFF_PW);
    uint2* QtW = (uint2*)(sm + OFF_QT);
    uint2* EW  = (uint2*)(sm + OFF_EW);
    float* pmax = sm + OFF_PM;   // [2][128]
    float* psum = sm + OFF_PS;   // [2][128]
    float* hm   = sm + OFF_PW;   // overlay after main loop, [128][154]

    const int tid = threadIdx.x;
    const int wid = tid >> 5, lane = tid & 31;
    const int g = lane >> 2, tig = lane & 3;
    const int half = wid >> 3;
    const int rb = (wid & 7) * 16;
    const int qoff = half * 32;
    const int jbO = half * 9;
    const int r0 = rb + g, r1 = rb + g + 8;
    const int b = blockIdx.y, a0 = blockIdx.x * 128;
    const size_t base = (size_t)b * Lseq * 160;

    // stage Ah pre-split: [128][160] floats -> AhW[r][p] uint2
    #pragma unroll 2
    for (int t = 0; t < 10; t++) {
        int idx = tid + t*512;
        int r = idx / 40, c4 = idx - r*40;
        float4 v = *(const float4*)&g_Ah[base + (size_t)(a0 + r)*160 + c4*4];
        uint32_t h0,l0,h1,l1;
        splitb2(v.x, v.y, h0, l0);
        splitb2(v.z, v.w, h1, l1);
        AhW[r*UA + 2*c4    ] = make_uint2(h0, l0);
        AhW[r*UA + 2*c4 + 1] = make_uint2(h1, l1);
    }

    float o[10][4];
    #pragma unroll
    for (int j = 0; j < 10; j++)
        #pragma unroll
        for (int e = 0; e < 4; e++) o[j][e] = 0.f;
    float m0 = -INFINITY, m1 = -INFINITY, l0s = 0.f, l1s = 0.f;

    for (int qt = 0; qt < 32; qt++) {
        const size_t qb = base + (size_t)qt * 64 * 160;
        const size_t qtb = (size_t)(b*32 + qt) * 160 * 64;
        // stage P pre-split transposed: PW[p][q]
        #pragma unroll
        for (int t = 0; t < 5; t++) {
            int idx = tid + t*512;
            int q = idx / 40, c4 = idx - q*40;
            float4 v = *(const float4*)&g_P[qb + (size_t)q*160 + c4*4];
            uint32_t h0,l0,h1,l1;
            splitb2(v.x, v.y, h0, l0);
            splitb2(v.z, v.w, h1, l1);
            PW[(2*c4    )*UP + q] = make_uint2(h0, l0);
            PW[(2*c4 + 1)*UP + q] = make_uint2(h1, l1);
        }
        // stage Qt pre-split transposed: QtW[p][col]  (g_Qt is [h][q])
        #pragma unroll
        for (int t = 0; t < 5; t++) {
            int idx = tid + t*512;
            int h = idx >> 4, c4 = idx & 15;
            float4 v = *(const float4*)&g_Qt[qtb + (size_t)h*64 + c4*4];
            uint32_t h0,l0,h1,l1;
            splitb2(v.x, v.y, h0, l0);
            splitb2(v.z, v.w, h1, l1);
            QtW[(2*c4    )*UQ + h] = make_uint2(h0, l0);
            QtW[(2*c4 + 1)*UQ + h] = make_uint2(h1, l1);
        }
        __syncthreads();

        // ---- S = Ah @ P^T : 16 rows x 32 q per warp, K=160, bf16 2-term ----
        float s[4][4];
        #pragma unroll
        for (int j = 0; j < 4; j++)
            #pragma unroll
            for (int e = 0; e < 4; e++) s[j][e] = 0.f;
        #pragma unroll 1
        for (int t = 0; t < 10; t++) {
            int p = t*8 + tig;
            uint2 A0 = AhW[r0*UA + p];
            uint2 A1 = AhW[r1*UA + p];
            uint2 A2 = AhW[r0*UA + p + 4];
            uint2 A3 = AhW[r1*UA + p + 4];
            #pragma unroll
            for (int j = 0; j < 4; j++) {
                int q = qoff + 8*j + g;
                uint2 B0 = PW[p*UP + q];
                uint2 B1 = PW[(p + 4)*UP + q];
                mma16(s[j], A0.x,A1.x,A2.x,A3.x, B0.x,B1.x);
                mma16(s[j], A0.x,A1.x,A2.x,A3.x, B0.y,B1.y);
                mma16(s[j], A0.y,A1.y,A2.y,A3.y, B0.x,B1.x);
            }
        }

        // ---- partial row max over this warp's 32 q ----
        float mx0 = -INFINITY, mx1 = -INFINITY;
        #pragma unroll
        for (int j = 0; j < 4; j++) {
            mx0 = fmaxf(mx0, fmaxf(s[j][0], s[j][1]));
            mx1 = fmaxf(mx1, fmaxf(s[j][2], s[j][3]));
        }
        mx0 = fmaxf(mx0, __shfl_xor_sync(0xffffffffu, mx0, 1));
        mx0 = fmaxf(mx0, __shfl_xor_sync(0xffffffffu, mx0, 2));
        mx1 = fmaxf(mx1, __shfl_xor_sync(0xffffffffu, mx1, 1));
        mx1 = fmaxf(mx1, __shfl_xor_sync(0xffffffffu, mx1, 2));
        if (tig == 0) {
            pmax[half*128 + r0] = mx0;
            pmax[half*128 + r1] = mx1;
        }
        __syncthreads();

        // ---- combined new max; rescale O; E (pre-split write) + partial sums ----
        float mn0 = fmaxf(m0, fmaxf(pmax[r0], pmax[128 + r0]));
        float mn1 = fmaxf(m1, fmaxf(pmax[r1], pmax[128 + r1]));
        float al0 = fexp(m0 - mn0), al1 = fexp(m1 - mn1);
        #pragma unroll
        for (int j = 0; j < 10; j++) {
            o[j][0] *= al0; o[j][1] *= al0;
            o[j][2] *= al1; o[j][3] *= al1;
        }
        float sum0 = 0.f, sum1 = 0.f;
        #pragma unroll
        for (int j = 0; j < 4; j++) {
            float e0 = fexp(s[j][0] - mn0);
            float e1 = fexp(s[j][1] - mn0);
            float e2 = fexp(s[j][2] - mn1);
            float e3 = fexp(s[j][3] - mn1);
            sum0 += e0 + e1; sum1 += e2 + e3;
            int pq = half*16 + 4*j + tig;
            uint32_t eh, el;
            splitb2(e0, e1, eh, el);
            EW[pq*UE + r0] = make_uint2(eh, el);
            splitb2(e2, e3, eh, el);
            EW[pq*UE + r1] = make_uint2(eh, el);
        }
        sum0 += __shfl_xor_sync(0xffffffffu, sum0, 1);
        sum0 += __shfl_xor_sync(0xffffffffu, sum0, 2);
        sum1 += __shfl_xor_sync(0xffffffffu, sum1, 1);
        sum1 += __shfl_xor_sync(0xffffffffu, sum1, 2);
        if (tig == 0) {
            psum[half*128 + r0] = sum0;
            psum[half*128 + r1] = sum1;
        }
        __syncthreads();
        l0s = l0s*al0 + psum[r0] + psum[128 + r0]; m0 = mn0;
        l1s = l1s*al1 + psum[r1] + psum[128 + r1]; m1 = mn1;

        // ---- O += E @ Qh : 16 rows x 80 h per warp, K=64, bf16 2-term ----
        #pragma unroll 1
        for (int t = 0; t < 4; t++) {
            int p = t*8 + tig;
            uint2 E0 = EW[p*UE + r0];
            uint2 E1 = EW[p*UE + r1];
            uint2 E2 = EW[(p + 4)*UE + r0];
            uint2 E3 = EW[(p + 4)*UE + r1];
            #pragma unroll
            for (int j = 0; j < 10; j++) {
                int col = 8*(jbO + j) + g;
                uint2 Q0 = QtW[p*UQ + col];
                uint2 Q1 = QtW[(p + 4)*UQ + col];
                mma16(o[j], E0.x,E1.x,E2.x,E3.x, Q0.x,Q1.x);
                mma16(o[j], E0.x,E1.x,E2.x,E3.x, Q0.y,Q1.y);
                mma16(o[j], E0.y,E1.y,E2.y,E3.y, Q0.x,Q1.x);
            }
        }
        __syncthreads();   // PW/QtW/EW free for next tile
    }

    // ---- normalize O into hm (overlay PW/QtW) ----
    {
        float inv0 = 1.f / l0s, inv1 = 1.f / l1s;
        #pragma unroll
        for (int j = 0; j < 10; j++) {
            int c = 8*(jbO + j) + 2*tig;
            if (c < Hk) {
                *(float2*)&hm[r0*ST_H + c] = make_float2(o[j][0]*inv0, o[j][1]*inv0);
                *(float2*)&hm[r1*ST_H + c] = make_float2(o[j][2]*inv1, o[j][3]*inv1);
            }
        }
    }
    __syncthreads();

    // ---- epilogue: T = relu([Ah, Hm] @ Wt + bt), f32x2 SIMT ----
    {
        const int tx = tid & 15, tyy = tid >> 4;   // tyy 0..31
        u64t acc2[4][5];
        #pragma unroll
        for (int jp = 0; jp < 5; jp++) {
            int p = tx + 16*jp;
            u64t bb = (p < 75) ? *(const u64t*)&bt[2*p] : 0ull;
            #pragma unroll
            for (int i = 0; i < 4; i++) acc2[i][jp] = bb;
        }
        // Ah part: reconstruct a = hi + lo from pre-split AhW
        for (int pp = 0; pp < 75; pp++) {
            u64t ae[4], ao[4];
            #pragma unroll
            for (int i = 0; i < 4; i++) {
                uint2 Av = AhW[(tyy + 32*i)*UA + pp];
                float ev = __uint_as_float(Av.x << 16) +
                           __uint_as_float(Av.y << 16);
                float ov = __uint_as_float(Av.x & 0xffff0000u) +
                           __uint_as_float(Av.y & 0xffff0000u);
                ae[i] = pack2(ev, ev);
                ao[i] = pack2(ov, ov);
            }
            #pragma unroll
            for (int jp = 0; jp < 5; jp++) {
                int p = tx + 16*jp;
                u64t w0 = (p < 75) ? *(const u64t*)&Wt[(size_t)(2*pp  )*Hk + 2*p] : 0ull;
                u64t w1 = (p < 75) ? *(const u64t*)&Wt[(size_t)(2*pp+1)*Hk + 2*p] : 0ull;
                #pragma unroll
                for (int i = 0; i < 4; i++) {
                    ffma2(acc2[i][jp], ae[i], w0);
                    ffma2(acc2[i][jp], ao[i], w1);
                }
            }
        }
        // Hm part
        for (int h = 0; h < Hk; h++) {
            u64t ovp[4];
            #pragma unroll
            for (int i = 0; i < 4; i++) {
                float ov = hm[(tyy + 32*i)*ST_H + h];
                ovp[i] = pack2(ov, ov);
            }
            #pragma unroll
            for (int jp = 0; jp < 5; jp++) {
                int p = tx + 16*jp;
                u64t w = (p < 75) ? *(const u64t*)&Wt[(size_t)(Hk + h)*Hk + 2*p] : 0ull;
                #pragma unroll
                for (int i = 0; i < 4; i++) ffma2(acc2[i][jp], ovp[i], w);
            }
        }
        #pragma unroll
        for (int i = 0; i < 4; i++)
            #pragma unroll
            for (int jp = 0; jp < 5; jp++) {
                int p = tx + 16*jp;
                if (p < 75) {
                    int r = tyy + 32*i;
                    float v0 = fmaxf(lo_f(acc2[i][jp]), 0.f);
                    float v1 = fmaxf(hi_f(acc2[i][jp]), 0.f);
                    *(u64t*)&out[((size_t)b*Lseq + a0 + r)*Hk + 2*p] = pack2(v0, v1);
                }
            }
    }
}

// ---------------------------------------------------------------------------
extern "C" void kernel_launch(void* const* d_in, const int* in_sizes, int n_in,
                              void* d_out, int out_size)
{
    const float* Q  = (const float*)d_in[0];
    const float* A  = (const float*)d_in[1];
    const float* Wi = (const float*)d_in[2];
    const float* Wu = (const float*)d_in[3];
    const float* Wg = (const float*)d_in[4];
    const float* Wt = (const float*)d_in[5];
    const float* bi = (const float*)d_in[6];
    const float* bu = (const float*)d_in[7];
    const float* bg = (const float*)d_in[8];
    const float* bt = (const float*)d_in[9];
    float* out = (float*)d_out;

    cudaFuncSetAttribute(attn_kernel,
                         cudaFuncAttributeMaxDynamicSharedMemorySize,
                         SMF_TOT * (int)sizeof(float));

    gate_kernel<<<1024, 256>>>(Q, A, Wi, Wu, Wg, bi, bu, bg);
    attn_kernel<<<dim3(16, Bq), 512, SMF_TOT * sizeof(float)>>>(Wt, bt, out);
}